// round 12
// baseline (speedup 1.0000x reference)
#include <cuda_runtime.h>
#include <math.h>

// Problem constants
#define B_    128
#define N_    32
#define T_    50
#define H_    128
#define NT_   1600           // N_*T_
#define HOPS_ 8

// Output layout: tuple (BW, BA, neigh_r) flattened in order
#define BW_OFF   ((size_t)0)
#define BA_OFF   ((size_t)(B_) * NT_)                       // 204800
#define NR_OFF   (BA_OFF + (size_t)(B_) * HOPS_ * NT_)      // 204800 + 1638400

// scratch: per-(b,hop,block) partial sums of exps + arrival counters
__device__ float g_part[B_ * HOPS_ * 50];
__device__ int   g_cnt[B_];          // zero-init; finisher resets -> replay-safe

// ---- packed f32x2 helpers (Blackwell FFMA2 path, PTX-only) -----------------
__device__ __forceinline__ unsigned long long pack2(float lo, float hi) {
    unsigned long long r;
    asm("mov.b64 %0, {%1, %2};" : "=l"(r) : "f"(lo), "f"(hi));
    return r;
}
__device__ __forceinline__ void unpack2(unsigned long long v, float& lo, float& hi) {
    asm("mov.b64 {%0, %1}, %2;" : "=f"(lo), "=f"(hi) : "l"(v));
}
__device__ __forceinline__ unsigned long long mul2(unsigned long long a,
                                                   unsigned long long b) {
    unsigned long long d;
    asm("mul.rn.f32x2 %0, %1, %2;" : "=l"(d) : "l"(a), "l"(b));
    return d;
}
__device__ __forceinline__ unsigned long long ffma2(unsigned long long a,
                                                    unsigned long long b,
                                                    unsigned long long c) {
    unsigned long long d;
    asm("fma.rn.f32x2 %0, %1, %2, %3;" : "=l"(d) : "l"(a), "l"(b), "l"(c));
    return d;
}

// ---------------------------------------------------------------------------
// K1: fully fused. neigh_r copy + logits + exp + per-block hop partials,
// then the LAST-ARRIVING block of each b (threadfence-reduction pattern)
// computes inv_s and normalizes that b's BA + writes BW.
// Block covers 16 n x 2 t = 32 rows of one b; 8 warps x 4 rows/warp sharing t.
// ---------------------------------------------------------------------------
#define SA_  132
#define ST_  64

__global__ __launch_bounds__(256, 3) void k1_fused(
    const float* __restrict__ node,   // [B, T, H]
    const float* __restrict__ neigh,  // [B, N, T, H]
    const int*   __restrict__ nn,     // [B]
    const float* __restrict__ W,      // [HOPS, H]
    const float* __restrict__ bias,   // [HOPS]
    float* __restrict__ out)
{
    __shared__ float stage[HOPS_ * SA_];   // [hop][toff][nloc][k]
    __shared__ float inv_s[HOPS_];
    __shared__ int   last_flag;

    const int tid  = threadIdx.x;
    const int wid  = tid >> 5;
    const int lane = tid & 31;

    // grid = B * 2 * 25 : bid -> (b, ng, tg)
    const int bid = blockIdx.x;
    const int b   = bid / 50;
    const int rem = bid - b * 50;        // block index within b: 0..49
    const int ng  = rem / 25;            // 0..1  -> n0 = ng*16
    const int tg  = rem - ng * 25;       // 0..24 -> t0 = tg*2
    const int n0  = ng * 16;
    const int t0  = tg * 2;

    const int nh   = wid >> 1;           // 0..3 : n sub-group
    const int toff = wid & 1;            // 0..1 : t within block
    const int t    = t0 + toff;
    const int nA   = n0 + nh * 4;        // first n of this warp

    // W packed as hop-pairs: wp[a2][c] = {W[2a2][4l+c], W[2a2+1][4l+c]}
    unsigned long long wp[4][4];
#pragma unroll
    for (int a2 = 0; a2 < 4; a2++) {
        const float4 wa = __ldg((const float4*)(W + (2 * a2)     * H_) + lane);
        const float4 wb = __ldg((const float4*)(W + (2 * a2 + 1) * H_) + lane);
        wp[a2][0] = pack2(wa.x, wb.x);
        wp[a2][1] = pack2(wa.y, wb.y);
        wp[a2][2] = pack2(wa.z, wb.z);
        wp[a2][3] = pack2(wa.w, wb.w);
    }

    // base row = (b, nA, t); successive rows step n by 1 -> +T_*H_ floats
    const size_t row0 = ((size_t)(b * N_ + nA) * T_ + t) * H_;
    const float4* nbase = (const float4*)(neigh + row0) + lane;
    float4*       obase = (float4*)(out + NR_OFF + row0) + lane;

    // one node row per warp, reused for all 4 rows
    const float4 u = __ldg((const float4*)(node + ((size_t)b * T_ + t) * H_) + lane);

    // batched streaming loads (MLP) + copy
    float4 v[4];
#pragma unroll
    for (int i = 0; i < 4; i++)
        v[i] = __ldcs(nbase + (size_t)i * (T_ * H_ / 4));
#pragma unroll
    for (int i = 0; i < 4; i++)
        __stcs(obase + (size_t)i * (T_ * H_ / 4), v[i]);

#pragma unroll
    for (int i = 0; i < 4; i++) {
        const int nloc = nh * 4 + i;     // 0..15

        const float px = v[i].x * u.x, py = v[i].y * u.y,
                    pz = v[i].z * u.z, pw = v[i].w * u.w;
        const unsigned long long d0 = pack2(px, px);
        const unsigned long long d1 = pack2(py, py);
        const unsigned long long d2 = pack2(pz, pz);
        const unsigned long long d3 = pack2(pw, pw);

        unsigned long long acc[4];
#pragma unroll
        for (int a2 = 0; a2 < 4; a2++) {
            acc[a2] = mul2(d0, wp[a2][0]);
            acc[a2] = ffma2(d1, wp[a2][1], acc[a2]);
            acc[a2] = ffma2(d2, wp[a2][2], acc[a2]);
            acc[a2] = ffma2(d3, wp[a2][3], acc[a2]);
        }

        float part[HOPS_];
        unpack2(acc[0], part[0], part[1]);
        unpack2(acc[1], part[2], part[3]);
        unpack2(acc[2], part[4], part[5]);
        unpack2(acc[3], part[6], part[7]);

        // ---- 14-shuffle fold reduction: stop at 4 residue-partials/hop ----
#pragma unroll
        for (int a = 0; a < HOPS_; a++)
            part[a] += __shfl_xor_sync(0xffffffffu, part[a], 16);

        float q0 = (lane < 16) ? part[0] : part[4];
        float q1 = (lane < 16) ? part[1] : part[5];
        float q2 = (lane < 16) ? part[2] : part[6];
        float q3 = (lane < 16) ? part[3] : part[7];
        q0 += __shfl_xor_sync(0xffffffffu, q0, 8);
        q1 += __shfl_xor_sync(0xffffffffu, q1, 8);
        q2 += __shfl_xor_sync(0xffffffffu, q2, 8);
        q3 += __shfl_xor_sync(0xffffffffu, q3, 8);

        float r0 = ((lane & 8) == 0) ? q0 : q2;
        float r1 = ((lane & 8) == 0) ? q1 : q3;
        r0 += __shfl_xor_sync(0xffffffffu, r0, 4);
        r1 += __shfl_xor_sync(0xffffffffu, r1, 4);

        // lane l holds residue-partial k=(l&3) of hop a=(l>>2)
        const float s = ((lane & 4) == 0) ? r0 : r1;
        stage[(lane >> 2) * SA_ + toff * ST_ + nloc * 4 + (lane & 3)] = s;
    }
    __syncthreads();

    // epilogue: warp a finishes hop a's 32 (n,t): LDS.128 + exp + BA store,
    // then butterfly-sums its 32 exps -> per-block partial (deterministic).
    {
        const int a    = wid;                      // hop
        const int tofe = lane >> 4;                // 0..1
        const int nle  = lane & 15;                // 0..15
        const float4 p = *(const float4*)&stage[a * SA_ + tofe * ST_ + nle * 4];
        const float dot = (p.x + p.y) + (p.z + p.w);
        const float rscale = rsqrtf((float)__ldg(nn));
        const float logit = (dot + __ldg(bias + a)) * rscale;
        // exp without max-subtraction: logits are O(1) by construction,
        // normalization cancels any shift exactly.
        const float ev = __expf(logit);
        out[BA_OFF + ((size_t)(b * HOPS_ + a)) * NT_
            + (size_t)(n0 + nle) * T_ + t0 + tofe] = ev;

        float ssum = ev;
#pragma unroll
        for (int off = 16; off; off >>= 1)
            ssum += __shfl_xor_sync(0xffffffffu, ssum, off);
        if (lane == 0)
            g_part[((size_t)(b * HOPS_ + a)) * 50 + rem] = ssum;
    }

    // ---- threadfence reduction: last-arriving block of b normalizes ----
    __threadfence();          // publish this thread's BA/g_part writes
    __syncthreads();          // all threads fenced before the ticket
    if (tid == 0) {
        const int old = atomicAdd(&g_cnt[b], 1);
        last_flag = (old == 49);
    }
    __syncthreads();
    if (!last_flag) return;

    __threadfence();          // acquire: see all 50 blocks' writes

    // inv_s: warp a reduces hop a's 50 partials (fixed order, deterministic)
    {
        const float* P = g_part + ((size_t)(b * HOPS_ + wid)) * 50;
        float s = (lane < 25) ? (P[lane] + P[lane + 25]) : 0.f;
#pragma unroll
        for (int off = 16; off; off >>= 1)
            s += __shfl_xor_sync(0xffffffffu, s, off);
        if (lane == 0) inv_s[wid] = 1.0f / s;
    }
    if (tid == 0) g_cnt[b] = 0;          // reset for next graph replay
    __syncthreads();

    // normalize this b's BA (8 hops x 400 float4 slots) + BW
    {
        float* BAb = out + BA_OFF + (size_t)b * HOPS_ * NT_;
        float* BW  = out + (size_t)b * NT_;
#pragma unroll
        for (int slot = 0; slot < 2; slot++) {
            const int s4 = tid + slot * 256;       // 0..511; active < 400
            if (s4 < NT_ / 4) {
                float4 va[HOPS_];
#pragma unroll
                for (int a = 0; a < HOPS_; a++)
                    va[a] = ((const float4*)(BAb + (size_t)a * NT_))[s4];
                float4 bw = make_float4(0.f, 0.f, 0.f, 0.f);
#pragma unroll
                for (int a = 0; a < HOPS_; a++) {
                    const float iv = inv_s[a];
                    float4 x = va[a];
                    x.x *= iv; x.y *= iv; x.z *= iv; x.w *= iv;
                    ((float4*)(BAb + (size_t)a * NT_))[s4] = x;
                    bw.x += x.x; bw.y += x.y; bw.z += x.z; bw.w += x.w;
                }
                ((float4*)BW)[s4] = bw;
            }
        }
    }
}

// ---------------------------------------------------------------------------
extern "C" void kernel_launch(void* const* d_in, const int* in_sizes, int n_in,
                              void* d_out, int out_size)
{
    const float* node  = (const float*)d_in[0];  // [B,T,H]
    const float* neigh = (const float*)d_in[1];  // [B,N,T,H]
    const int*   nn    = (const int*)  d_in[2];  // [B]
    const float* W     = (const float*)d_in[3];  // [HOPS,H]
    const float* bias  = (const float*)d_in[4];  // [HOPS]
    float* out = (float*)d_out;

    (void)in_sizes; (void)n_in; (void)out_size;

    // single fused kernel: grid = B * 2 * 25 = 6400 blocks
    k1_fused<<<B_ * 50, 256>>>(node, neigh, nn, W, bias, out);
}

// round 13
// speedup vs baseline: 1.3165x; 1.3165x over previous
#include <cuda_runtime.h>
#include <math.h>

// Problem constants
#define B_    128
#define N_    32
#define T_    50
#define H_    128
#define NT_   1600           // N_*T_
#define HOPS_ 8

// Output layout: tuple (BW, BA, neigh_r) flattened in order
#define BW_OFF   ((size_t)0)
#define BA_OFF   ((size_t)(B_) * NT_)                       // 204800
#define NR_OFF   (BA_OFF + (size_t)(B_) * HOPS_ * NT_)      // 204800 + 1638400

// ---- packed f32x2 helpers (Blackwell FFMA2 path, PTX-only) -----------------
__device__ __forceinline__ unsigned long long pack2(float lo, float hi) {
    unsigned long long r;
    asm("mov.b64 %0, {%1, %2};" : "=l"(r) : "f"(lo), "f"(hi));
    return r;
}
__device__ __forceinline__ void unpack2(unsigned long long v, float& lo, float& hi) {
    asm("mov.b64 {%0, %1}, %2;" : "=f"(lo), "=f"(hi) : "l"(v));
}
__device__ __forceinline__ unsigned long long mul2(unsigned long long a,
                                                   unsigned long long b) {
    unsigned long long d;
    asm("mul.rn.f32x2 %0, %1, %2;" : "=l"(d) : "l"(a), "l"(b));
    return d;
}
__device__ __forceinline__ unsigned long long ffma2(unsigned long long a,
                                                    unsigned long long b,
                                                    unsigned long long c) {
    unsigned long long d;
    asm("fma.rn.f32x2 %0, %1, %2, %3;" : "=l"(d) : "l"(a), "l"(b), "l"(c));
    return d;
}

// ---------------------------------------------------------------------------
// K1: fused neigh_r copy + logits + exp. (R10 structure — proven best)
// Block covers 16 n x 2 t = 32 rows of one b. 8 warps x 4 rows/warp; a warp's
// 4 rows share t -> node row u loaded ONCE per warp.
// CHANGE vs R10: nr stores use __stwt (write-through, no L2 allocate) so the
// 105 MB write stream does not evict the BA region that K2 re-reads.
// ---------------------------------------------------------------------------
#define SA_  132
#define ST_  64

__global__ __launch_bounds__(256, 3) void k1_fused(
    const float* __restrict__ node,   // [B, T, H]
    const float* __restrict__ neigh,  // [B, N, T, H]
    const int*   __restrict__ nn,     // [B]
    const float* __restrict__ W,      // [HOPS, H]
    const float* __restrict__ bias,   // [HOPS]
    float* __restrict__ out)
{
    __shared__ float stage[HOPS_ * SA_];   // [hop][toff][nloc][k]

    const int tid  = threadIdx.x;
    const int wid  = tid >> 5;
    const int lane = tid & 31;

    // grid = B * 2 * 25 : bid -> (b, ng, tg)
    const int bid = blockIdx.x;
    const int b   = bid / 50;
    const int rem = bid - b * 50;
    const int ng  = rem / 25;            // 0..1  -> n0 = ng*16
    const int tg  = rem - ng * 25;       // 0..24 -> t0 = tg*2
    const int n0  = ng * 16;
    const int t0  = tg * 2;

    const int nh   = wid >> 1;           // 0..3 : n sub-group
    const int toff = wid & 1;            // 0..1 : t within block
    const int t    = t0 + toff;
    const int nA   = n0 + nh * 4;        // first n of this warp

    // W packed as hop-pairs: wp[a2][c] = {W[2a2][4l+c], W[2a2+1][4l+c]}
    unsigned long long wp[4][4];
#pragma unroll
    for (int a2 = 0; a2 < 4; a2++) {
        const float4 wa = __ldg((const float4*)(W + (2 * a2)     * H_) + lane);
        const float4 wb = __ldg((const float4*)(W + (2 * a2 + 1) * H_) + lane);
        wp[a2][0] = pack2(wa.x, wb.x);
        wp[a2][1] = pack2(wa.y, wb.y);
        wp[a2][2] = pack2(wa.z, wb.z);
        wp[a2][3] = pack2(wa.w, wb.w);
    }

    // base row = (b, nA, t); successive rows step n by 1 -> +T_*H_ floats
    const size_t row0 = ((size_t)(b * N_ + nA) * T_ + t) * H_;
    const float4* nbase = (const float4*)(neigh + row0) + lane;
    float4*       obase = (float4*)(out + NR_OFF + row0) + lane;

    // one node row per warp, reused for all 4 rows
    const float4 u = __ldg((const float4*)(node + ((size_t)b * T_ + t) * H_) + lane);

    // batched streaming loads (MLP) + write-through copy (no L2 allocate)
    float4 v[4];
#pragma unroll
    for (int i = 0; i < 4; i++)
        v[i] = __ldcs(nbase + (size_t)i * (T_ * H_ / 4));
#pragma unroll
    for (int i = 0; i < 4; i++)
        __stwt(obase + (size_t)i * (T_ * H_ / 4), v[i]);

#pragma unroll
    for (int i = 0; i < 4; i++) {
        const int nloc = nh * 4 + i;     // 0..15

        const float px = v[i].x * u.x, py = v[i].y * u.y,
                    pz = v[i].z * u.z, pw = v[i].w * u.w;
        const unsigned long long d0 = pack2(px, px);
        const unsigned long long d1 = pack2(py, py);
        const unsigned long long d2 = pack2(pz, pz);
        const unsigned long long d3 = pack2(pw, pw);

        unsigned long long acc[4];
#pragma unroll
        for (int a2 = 0; a2 < 4; a2++) {
            acc[a2] = mul2(d0, wp[a2][0]);
            acc[a2] = ffma2(d1, wp[a2][1], acc[a2]);
            acc[a2] = ffma2(d2, wp[a2][2], acc[a2]);
            acc[a2] = ffma2(d3, wp[a2][3], acc[a2]);
        }

        float part[HOPS_];
        unpack2(acc[0], part[0], part[1]);
        unpack2(acc[1], part[2], part[3]);
        unpack2(acc[2], part[4], part[5]);
        unpack2(acc[3], part[6], part[7]);

        // ---- 14-shuffle fold reduction: stop at 4 residue-partials/hop ----
#pragma unroll
        for (int a = 0; a < HOPS_; a++)
            part[a] += __shfl_xor_sync(0xffffffffu, part[a], 16);

        float q0 = (lane < 16) ? part[0] : part[4];
        float q1 = (lane < 16) ? part[1] : part[5];
        float q2 = (lane < 16) ? part[2] : part[6];
        float q3 = (lane < 16) ? part[3] : part[7];
        q0 += __shfl_xor_sync(0xffffffffu, q0, 8);
        q1 += __shfl_xor_sync(0xffffffffu, q1, 8);
        q2 += __shfl_xor_sync(0xffffffffu, q2, 8);
        q3 += __shfl_xor_sync(0xffffffffu, q3, 8);

        float r0 = ((lane & 8) == 0) ? q0 : q2;
        float r1 = ((lane & 8) == 0) ? q1 : q3;
        r0 += __shfl_xor_sync(0xffffffffu, r0, 4);
        r1 += __shfl_xor_sync(0xffffffffu, r1, 4);

        // lane l holds residue-partial k=(l&3) of hop a=(l>>2)
        const float s = ((lane & 4) == 0) ? r0 : r1;
        stage[(lane >> 2) * SA_ + toff * ST_ + nloc * 4 + (lane & 3)] = s;
    }
    __syncthreads();

    // epilogue: 256 threads finish 8 hops x 32 (n,t): LDS.128 + 3 FADD + exp
    {
        const int a    = tid >> 5;                 // hop
        const int j    = tid & 31;                 // row slot
        const int tofe = j >> 4;                   // 0..1
        const int nle  = j & 15;                   // 0..15
        const float4 p = *(const float4*)&stage[a * SA_ + tofe * ST_ + nle * 4];
        const float dot = (p.x + p.y) + (p.z + p.w);
        const float rscale = rsqrtf((float)__ldg(nn));
        const float logit = (dot + __ldg(bias + a)) * rscale;
        // exp without max-subtraction: logits are O(1) by construction,
        // normalization cancels any shift exactly.
        out[BA_OFF + ((size_t)(b * HOPS_ + a)) * NT_
            + (size_t)(n0 + nle) * T_ + t0 + tofe] = __expf(logit);
    }
}

// ---------------------------------------------------------------------------
// K2: SINGLE-PASS per-b softmax-normalize + BW. (unchanged from R10)
// One block per b, 512 threads; thread s<400 owns float4 slot s of ALL 8 hops.
// ---------------------------------------------------------------------------
#define KSA_ 68   // stage stride per hop: bank = 4a + 4wid + k (conflict-free)

__global__ __launch_bounds__(512) void k2_softmax_bw(float* __restrict__ out)
{
    __shared__ float stage[HOPS_ * KSA_];   // [hop][wid*4 + k]
    __shared__ float inv_s[HOPS_];

    const int tid  = threadIdx.x;
    const int wid  = tid >> 5;              // 0..15
    const int lane = tid & 31;
    const int b    = blockIdx.x;
    const bool act = tid < NT_ / 4;         // 400 active slots

    float* BAb = out + BA_OFF + (size_t)b * HOPS_ * NT_;

    // ---- load all 8 hops' float4 for this slot (batched, MLP=8) ----
    float4 va[HOPS_];
#pragma unroll
    for (int a = 0; a < HOPS_; a++)
        va[a] = act ? ((const float4*)(BAb + (size_t)a * NT_))[tid]
                    : make_float4(0.f, 0.f, 0.f, 0.f);

    // ---- per-hop partial sums ----
    float part[HOPS_];
#pragma unroll
    for (int a = 0; a < HOPS_; a++)
        part[a] = (va[a].x + va[a].y) + (va[a].z + va[a].w);

    // ---- 14-shuffle fold reduction: 8 sums over 32 lanes -> 4 residues/hop
#pragma unroll
    for (int a = 0; a < HOPS_; a++)
        part[a] += __shfl_xor_sync(0xffffffffu, part[a], 16);

    float q0 = (lane < 16) ? part[0] : part[4];
    float q1 = (lane < 16) ? part[1] : part[5];
    float q2 = (lane < 16) ? part[2] : part[6];
    float q3 = (lane < 16) ? part[3] : part[7];
    q0 += __shfl_xor_sync(0xffffffffu, q0, 8);
    q1 += __shfl_xor_sync(0xffffffffu, q1, 8);
    q2 += __shfl_xor_sync(0xffffffffu, q2, 8);
    q3 += __shfl_xor_sync(0xffffffffu, q3, 8);

    float r0 = ((lane & 8) == 0) ? q0 : q2;
    float r1 = ((lane & 8) == 0) ? q1 : q3;
    r0 += __shfl_xor_sync(0xffffffffu, r0, 4);
    r1 += __shfl_xor_sync(0xffffffffu, r1, 4);

    // lane l holds residue k=(l&3) of hop a=(l>>2)
    const float s = ((lane & 4) == 0) ? r0 : r1;
    stage[(lane >> 2) * KSA_ + wid * 4 + (lane & 3)] = s;
    __syncthreads();

    // ---- 8 warps finish: warp a reduces 64 residues of hop a (fixed order)
    if (wid < HOPS_) {
        float t = stage[wid * KSA_ + lane] + stage[wid * KSA_ + 32 + lane];
#pragma unroll
        for (int off = 16; off; off >>= 1)
            t += __shfl_xor_sync(0xffffffffu, t, off);
        if (lane == 0) inv_s[wid] = 1.0f / t;
    }
    __syncthreads();

    // ---- normalize registers, store BA + BW ----
    if (act) {
        float4 acc = make_float4(0.f, 0.f, 0.f, 0.f);
#pragma unroll
        for (int a = 0; a < HOPS_; a++) {
            const float iv = inv_s[a];
            float4 v = va[a];
            v.x *= iv; v.y *= iv; v.z *= iv; v.w *= iv;
            ((float4*)(BAb + (size_t)a * NT_))[tid] = v;
            acc.x += v.x; acc.y += v.y; acc.z += v.z; acc.w += v.w;
        }
        ((float4*)(out + (size_t)b * NT_))[tid] = acc;   // BW
    }
}

// ---------------------------------------------------------------------------
extern "C" void kernel_launch(void* const* d_in, const int* in_sizes, int n_in,
                              void* d_out, int out_size)
{
    const float* node  = (const float*)d_in[0];  // [B,T,H]
    const float* neigh = (const float*)d_in[1];  // [B,N,T,H]
    const int*   nn    = (const int*)  d_in[2];  // [B]
    const float* W     = (const float*)d_in[3];  // [HOPS,H]
    const float* bias  = (const float*)d_in[4];  // [HOPS]
    float* out = (float*)d_out;

    (void)in_sizes; (void)n_in; (void)out_size;

    // K1: grid = B * 2 * 25 = 6400 blocks (16 n x 2 t per block)
    k1_fused<<<B_ * 50, 256>>>(node, neigh, nn, W, bias, out);
    // K2: one block per b, 512 threads, single pass
    k2_softmax_bw<<<B_, 512>>>(out);
}

// round 15
// speedup vs baseline: 1.3827x; 1.0503x over previous
#include <cuda_runtime.h>
#include <math.h>

// Problem constants
#define B_    128
#define N_    32
#define T_    50
#define H_    128
#define NT_   1600           // N_*T_
#define HOPS_ 8

// Output layout: tuple (BW, BA, neigh_r) flattened in order
#define BW_OFF   ((size_t)0)
#define BA_OFF   ((size_t)(B_) * NT_)                       // 204800
#define NR_OFF   (BA_OFF + (size_t)(B_) * HOPS_ * NT_)      // 204800 + 1638400

// ---- packed f32x2 helpers (Blackwell FFMA2 path, PTX-only) -----------------
__device__ __forceinline__ unsigned long long pack2(float lo, float hi) {
    unsigned long long r;
    asm("mov.b64 %0, {%1, %2};" : "=l"(r) : "f"(lo), "f"(hi));
    return r;
}
__device__ __forceinline__ void unpack2(unsigned long long v, float& lo, float& hi) {
    asm("mov.b64 {%0, %1}, %2;" : "=f"(lo), "=f"(hi) : "l"(v));
}
__device__ __forceinline__ unsigned long long mul2(unsigned long long a,
                                                   unsigned long long b) {
    unsigned long long d;
    asm("mul.rn.f32x2 %0, %1, %2;" : "=l"(d) : "l"(a), "l"(b));
    return d;
}
__device__ __forceinline__ unsigned long long ffma2(unsigned long long a,
                                                    unsigned long long b,
                                                    unsigned long long c) {
    unsigned long long d;
    asm("fma.rn.f32x2 %0, %1, %2, %3;" : "=l"(d) : "l"(a), "l"(b), "l"(c));
    return d;
}

// ---------------------------------------------------------------------------
// K1: fused neigh_r copy + logits + exp. (R10 structure — proven best; __stcs.)
// Block covers 16 n x 2 t = 32 rows of one b; 8 warps x 4 rows/warp sharing t
// -> node row u loaded ONCE per warp.
// PDL: trigger the dependent K2 launch at block end.
// ---------------------------------------------------------------------------
#define SA_  132
#define ST_  64

__global__ __launch_bounds__(256, 3) void k1_fused(
    const float* __restrict__ node,   // [B, T, H]
    const float* __restrict__ neigh,  // [B, N, T, H]
    const int*   __restrict__ nn,     // [B]
    const float* __restrict__ W,      // [HOPS, H]
    const float* __restrict__ bias,   // [HOPS]
    float* __restrict__ out)
{
    __shared__ float stage[HOPS_ * SA_];   // [hop][toff][nloc][k]

    const int tid  = threadIdx.x;
    const int wid  = tid >> 5;
    const int lane = tid & 31;

    // grid = B * 2 * 25 : bid -> (b, ng, tg)
    const int bid = blockIdx.x;
    const int b   = bid / 50;
    const int rem = bid - b * 50;
    const int ng  = rem / 25;            // 0..1  -> n0 = ng*16
    const int tg  = rem - ng * 25;       // 0..24 -> t0 = tg*2
    const int n0  = ng * 16;
    const int t0  = tg * 2;

    const int nh   = wid >> 1;           // 0..3 : n sub-group
    const int toff = wid & 1;            // 0..1 : t within block
    const int t    = t0 + toff;
    const int nA   = n0 + nh * 4;        // first n of this warp

    // W packed as hop-pairs: wp[a2][c] = {W[2a2][4l+c], W[2a2+1][4l+c]}
    unsigned long long wp[4][4];
#pragma unroll
    for (int a2 = 0; a2 < 4; a2++) {
        const float4 wa = __ldg((const float4*)(W + (2 * a2)     * H_) + lane);
        const float4 wb = __ldg((const float4*)(W + (2 * a2 + 1) * H_) + lane);
        wp[a2][0] = pack2(wa.x, wb.x);
        wp[a2][1] = pack2(wa.y, wb.y);
        wp[a2][2] = pack2(wa.z, wb.z);
        wp[a2][3] = pack2(wa.w, wb.w);
    }

    // base row = (b, nA, t); successive rows step n by 1 -> +T_*H_ floats
    const size_t row0 = ((size_t)(b * N_ + nA) * T_ + t) * H_;
    const float4* nbase = (const float4*)(neigh + row0) + lane;
    float4*       obase = (float4*)(out + NR_OFF + row0) + lane;

    // one node row per warp, reused for all 4 rows
    const float4 u = __ldg((const float4*)(node + ((size_t)b * T_ + t) * H_) + lane);

    // batched streaming loads (MLP) + streaming copy
    float4 v[4];
#pragma unroll
    for (int i = 0; i < 4; i++)
        v[i] = __ldcs(nbase + (size_t)i * (T_ * H_ / 4));
#pragma unroll
    for (int i = 0; i < 4; i++)
        __stcs(obase + (size_t)i * (T_ * H_ / 4), v[i]);

#pragma unroll
    for (int i = 0; i < 4; i++) {
        const int nloc = nh * 4 + i;     // 0..15

        const float px = v[i].x * u.x, py = v[i].y * u.y,
                    pz = v[i].z * u.z, pw = v[i].w * u.w;
        const unsigned long long d0 = pack2(px, px);
        const unsigned long long d1 = pack2(py, py);
        const unsigned long long d2 = pack2(pz, pz);
        const unsigned long long d3 = pack2(pw, pw);

        unsigned long long acc[4];
#pragma unroll
        for (int a2 = 0; a2 < 4; a2++) {
            acc[a2] = mul2(d0, wp[a2][0]);
            acc[a2] = ffma2(d1, wp[a2][1], acc[a2]);
            acc[a2] = ffma2(d2, wp[a2][2], acc[a2]);
            acc[a2] = ffma2(d3, wp[a2][3], acc[a2]);
        }

        float part[HOPS_];
        unpack2(acc[0], part[0], part[1]);
        unpack2(acc[1], part[2], part[3]);
        unpack2(acc[2], part[4], part[5]);
        unpack2(acc[3], part[6], part[7]);

        // ---- 14-shuffle fold reduction: stop at 4 residue-partials/hop ----
#pragma unroll
        for (int a = 0; a < HOPS_; a++)
            part[a] += __shfl_xor_sync(0xffffffffu, part[a], 16);

        float q0 = (lane < 16) ? part[0] : part[4];
        float q1 = (lane < 16) ? part[1] : part[5];
        float q2 = (lane < 16) ? part[2] : part[6];
        float q3 = (lane < 16) ? part[3] : part[7];
        q0 += __shfl_xor_sync(0xffffffffu, q0, 8);
        q1 += __shfl_xor_sync(0xffffffffu, q1, 8);
        q2 += __shfl_xor_sync(0xffffffffu, q2, 8);
        q3 += __shfl_xor_sync(0xffffffffu, q3, 8);

        float r0 = ((lane & 8) == 0) ? q0 : q2;
        float r1 = ((lane & 8) == 0) ? q1 : q3;
        r0 += __shfl_xor_sync(0xffffffffu, r0, 4);
        r1 += __shfl_xor_sync(0xffffffffu, r1, 4);

        // lane l holds residue-partial k=(l&3) of hop a=(l>>2)
        const float s = ((lane & 4) == 0) ? r0 : r1;
        stage[(lane >> 2) * SA_ + toff * ST_ + nloc * 4 + (lane & 3)] = s;
    }
    __syncthreads();

    // epilogue: 256 threads finish 8 hops x 32 (n,t): LDS.128 + 3 FADD + exp
    {
        const int a    = tid >> 5;                 // hop
        const int j    = tid & 31;                 // row slot
        const int tofe = j >> 4;                   // 0..1
        const int nle  = j & 15;                   // 0..15
        const float4 p = *(const float4*)&stage[a * SA_ + tofe * ST_ + nle * 4];
        const float dot = (p.x + p.y) + (p.z + p.w);
        const float rscale = rsqrtf((float)__ldg(nn));
        const float logit = (dot + __ldg(bias + a)) * rscale;
        // exp without max-subtraction: logits are O(1) by construction,
        // normalization cancels any shift exactly.
        out[BA_OFF + ((size_t)(b * HOPS_ + a)) * NT_
            + (size_t)(n0 + nle) * T_ + t0 + tofe] = __expf(logit);
    }

    // PDL: allow the dependent K2 grid to begin launching
    cudaTriggerProgrammaticLaunchCompletion();
}

// ---------------------------------------------------------------------------
// K2: SINGLE-PASS per-b softmax-normalize + BW. (unchanged from R10)
// One block per b, 512 threads; thread s<400 owns float4 slot s of ALL 8 hops.
// PDL: grid-dependency sync at the head (K1 writes must be visible).
// ---------------------------------------------------------------------------
#define KSA_ 68   // stage stride per hop: bank = 4a + 4wid + k (conflict-free)

__global__ __launch_bounds__(512) void k2_softmax_bw(float* __restrict__ out)
{
    __shared__ float stage[HOPS_ * KSA_];   // [hop][wid*4 + k]
    __shared__ float inv_s[HOPS_];

    cudaGridDependencySynchronize();        // wait for K1 completion/visibility

    const int tid  = threadIdx.x;
    const int wid  = tid >> 5;              // 0..15
    const int lane = tid & 31;
    const int b    = blockIdx.x;
    const bool act = tid < NT_ / 4;         // 400 active slots

    float* BAb = out + BA_OFF + (size_t)b * HOPS_ * NT_;

    // ---- load all 8 hops' float4 for this slot (batched, MLP=8) ----
    float4 va[HOPS_];
#pragma unroll
    for (int a = 0; a < HOPS_; a++)
        va[a] = act ? ((const float4*)(BAb + (size_t)a * NT_))[tid]
                    : make_float4(0.f, 0.f, 0.f, 0.f);

    // ---- per-hop partial sums ----
    float part[HOPS_];
#pragma unroll
    for (int a = 0; a < HOPS_; a++)
        part[a] = (va[a].x + va[a].y) + (va[a].z + va[a].w);

    // ---- 14-shuffle fold reduction: 8 sums over 32 lanes -> 4 residues/hop
#pragma unroll
    for (int a = 0; a < HOPS_; a++)
        part[a] += __shfl_xor_sync(0xffffffffu, part[a], 16);

    float q0 = (lane < 16) ? part[0] : part[4];
    float q1 = (lane < 16) ? part[1] : part[5];
    float q2 = (lane < 16) ? part[2] : part[6];
    float q3 = (lane < 16) ? part[3] : part[7];
    q0 += __shfl_xor_sync(0xffffffffu, q0, 8);
    q1 += __shfl_xor_sync(0xffffffffu, q1, 8);
    q2 += __shfl_xor_sync(0xffffffffu, q2, 8);
    q3 += __shfl_xor_sync(0xffffffffu, q3, 8);

    float r0 = ((lane & 8) == 0) ? q0 : q2;
    float r1 = ((lane & 8) == 0) ? q1 : q3;
    r0 += __shfl_xor_sync(0xffffffffu, r0, 4);
    r1 += __shfl_xor_sync(0xffffffffu, r1, 4);

    // lane l holds residue k=(l&3) of hop a=(l>>2)
    const float s = ((lane & 4) == 0) ? r0 : r1;
    stage[(lane >> 2) * KSA_ + wid * 4 + (lane & 3)] = s;
    __syncthreads();

    // ---- 8 warps finish: warp a reduces 64 residues of hop a (fixed order)
    if (wid < HOPS_) {
        float t = stage[wid * KSA_ + lane] + stage[wid * KSA_ + 32 + lane];
#pragma unroll
        for (int off = 16; off; off >>= 1)
            t += __shfl_xor_sync(0xffffffffu, t, off);
        if (lane == 0) inv_s[wid] = 1.0f / t;
    }
    __syncthreads();

    // ---- normalize registers, store BA + BW ----
    if (act) {
        float4 acc = make_float4(0.f, 0.f, 0.f, 0.f);
#pragma unroll
        for (int a = 0; a < HOPS_; a++) {
            const float iv = inv_s[a];
            float4 v = va[a];
            v.x *= iv; v.y *= iv; v.z *= iv; v.w *= iv;
            ((float4*)(BAb + (size_t)a * NT_))[tid] = v;
            acc.x += v.x; acc.y += v.y; acc.z += v.z; acc.w += v.w;
        }
        ((float4*)(out + (size_t)b * NT_))[tid] = acc;   // BW
    }
}

// ---------------------------------------------------------------------------
extern "C" void kernel_launch(void* const* d_in, const int* in_sizes, int n_in,
                              void* d_out, int out_size)
{
    const float* node  = (const float*)d_in[0];  // [B,T,H]
    const float* neigh = (const float*)d_in[1];  // [B,N,T,H]
    const int*   nn    = (const int*)  d_in[2];  // [B]
    const float* W     = (const float*)d_in[3];  // [HOPS,H]
    const float* bias  = (const float*)d_in[4];  // [HOPS]
    float* out = (float*)d_out;

    (void)in_sizes; (void)n_in; (void)out_size;

    // K1: grid = B * 2 * 25 = 6400 blocks (16 n x 2 t per block)
    k1_fused<<<B_ * 50, 256>>>(node, neigh, nn, W, bias, out);

    // K2 with Programmatic Dependent Launch: overlap launch with K1 tail
    cudaLaunchConfig_t cfg = {};
    cfg.gridDim  = dim3(B_);
    cfg.blockDim = dim3(512);
    cfg.dynamicSmemBytes = 0;
    cudaLaunchAttribute attrs[1];
    attrs[0].id = cudaLaunchAttributeProgrammaticStreamSerialization;
    attrs[0].val.programmaticStreamSerializationAllowed = 1;
    cfg.attrs = attrs;
    cfg.numAttrs = 1;
    cudaLaunchKernelEx(&cfg, k2_softmax_bw, out);
}